// round 8
// baseline (speedup 1.0000x reference)
#include <cuda_runtime.h>
#include <cuda_pipeline.h>

// WidthAP: out[b,0,i,h] = sum_{j=0..4} x[b,0,i+j,h] * attn[b,i+j]
// x: (32,1,2052,768) fp32, attn: (32,2052) fp32, out: (32,1,2048,768) fp32.
//
// cp.async (LDGSTS) staged pipeline: DRAM->SMEM copies carry the MLP with
// zero register cost; 4-stage ring keeps 2 full 24KB stages in flight per
// CTA at all times. Each thread owns one float4 H-lane, so every smem cell
// is written and read by the same thread -> no in-loop __syncthreads.

#define LENGTH   2048
#define WIDTH    5
#define PADDED   (LENGTH + WIDTH - 1)   // 2052
#define BATCH    32
#define HDIM     768
#define H4       (HDIM / 4)             // 192 float4 lanes
#define ITILE    128                    // rows per block -> 512 CTAs, 3% halo
#define NTILES   (LENGTH / ITILE)       // 16
#define SROWS    8                      // rows per pipeline stage (24 KB)
#define NSTAGES  4                      // smem ring depth
#define NBATCH   (ITILE / SROWS)        // 16 consume batches
#define NLOAD    (ITILE / SROWS + 1)    // 17 load stages (covers halo rows)

#define W_BYTES   544                   // 132 floats, padded to 16B multiple
#define SMEM_SIZE (W_BYTES + NSTAGES * SROWS * H4 * 16)  // 98848 B

__device__ __forceinline__ float4 f4_scale(float4 v, float s) {
    return make_float4(v.x * s, v.y * s, v.z * s, v.w * s);
}
__device__ __forceinline__ float4 f4_add(float4 a, float4 b) {
    return make_float4(a.x + b.x, a.y + b.y, a.z + b.z, a.w + b.w);
}

extern __shared__ unsigned char smem_raw[];

__global__ __launch_bounds__(H4) void widthap_kernel(
    const float4* __restrict__ x,      // (B, PADDED, H4)
    const float*  __restrict__ attn,   // (B, PADDED)
    float4*       __restrict__ out)    // (B, LENGTH, H4)
{
    float*  w   = (float*)smem_raw;                  // 132 weights
    float4* buf = (float4*)(smem_raw + W_BYTES);     // [NSTAGES][SROWS][H4]

    const int lane = threadIdx.x;          // 0..191, one float4 column
    const int tile = blockIdx.x;           // 0..15
    const int b    = blockIdx.y;           // 0..31
    const int i0   = tile * ITILE;

    for (int k = lane; k < ITILE + WIDTH - 1; k += H4)
        w[k] = attn[b * PADDED + i0 + k];
    __syncthreads();

    const float4* xb = x + (long)b * PADDED * H4 + lane;  // batch base, this lane
    float4*       op = out + ((long)b * LENGTH + i0) * H4 + lane;

    // Issue one 8-row stage of cp.async (rows clamped at tensor edge; the
    // clamped rows are never consumed, clamping only keeps reads in-bounds).
    auto issue_stage = [&](int s) {
        float4* dst = buf + ((s % NSTAGES) * SROWS) * H4 + lane;
        const int gbase = i0 + s * SROWS;
        #pragma unroll
        for (int r = 0; r < SROWS; r++) {
            int g = gbase + r;
            if (g > PADDED - 1) g = PADDED - 1;
            __pipeline_memcpy_async(dst + r * H4, xb + (long)g * H4, 16);
        }
        __pipeline_commit();
    };

    issue_stage(0);
    issue_stage(1);
    issue_stage(2);

    // Wait for stage 0, prime the 5-deep weighted window (x rows 0..3).
    __pipeline_wait_prior(2);
    float4 v0 = f4_scale(buf[0 * H4 + lane], w[0]);
    float4 v1 = f4_scale(buf[1 * H4 + lane], w[1]);
    float4 v2 = f4_scale(buf[2 * H4 + lane], w[2]);
    float4 v3 = f4_scale(buf[3 * H4 + lane], w[3]);

    for (int m = 0; m < NBATCH; m++) {
        // Keep the pipe full: issue stage m+3 (or an empty group to keep
        // the commit count uniform for wait_prior accounting).
        if (m + 3 < NLOAD) issue_stage(m + 3);
        else               __pipeline_commit();

        // Ensure stages 0..m+1 have landed; stages m+2, m+3 stay in flight.
        __pipeline_wait_prior(2);

        // Outputs m*8 .. m*8+7 consume x rows m*8 .. m*8+11 (stages m, m+1).
        #pragma unroll
        for (int u = 0; u < SROWS; u++) {
            const int r4   = m * SROWS + 4 + u;             // feeding x row
            const int slot = (r4 >> 3) & (NSTAGES - 1);
            float4 xv = buf[(slot * SROWS + (r4 & (SROWS - 1))) * H4 + lane];
            float4 v4 = f4_scale(xv, w[r4]);
            __stcs(op + (m * SROWS + u) * H4,
                   f4_add(f4_add(f4_add(v0, v1), f4_add(v2, v3)), v4));
            v0 = v1; v1 = v2; v2 = v3; v3 = v4;
        }
    }
}

extern "C" void kernel_launch(void* const* d_in, const int* in_sizes, int n_in,
                              void* d_out, int out_size)
{
    const float4* x    = (const float4*)d_in[0];
    const float*  attn = (const float*)d_in[1];
    float4*       out  = (float4*)d_out;

    cudaFuncSetAttribute(widthap_kernel,
                         cudaFuncAttributeMaxDynamicSharedMemorySize, SMEM_SIZE);

    dim3 grid(NTILES, BATCH);
    widthap_kernel<<<grid, H4, SMEM_SIZE>>>(x, attn, out);
}